// round 12
// baseline (speedup 1.0000x reference)
#include <cuda_runtime.h>
#include <cuda_fp16.h>
#include <math_constants.h>
#include <cstdint>

#define BB 1024
#define LL 256
#define DD 64
#define TDIM 100
#define NTHR 64
#define NINT 65
#define NT 1024          // weight-table intervals (table has NT+1 entries)
#define MBLK 24          // m-table builder blocks (24 x 1024 = 24576 entries)
#define MENT (MBLK * 1024)   // covers half patterns up to 384.0 (x < 256.0 always)
#define NSETUP (NINT + 5 + MBLK)   // 94 setup blocks

// Scratch in __device__ globals (no allocations allowed).
// Row m = 16 uint4 per plane, each {U01,U23,V01,V23} (half2 words):
//   P: V'_m = V_m + V0 + 2*b2   (always-loaded operand)
//   S: V'_m = V_m - V0          (predicated; row contribution exactly 0 when x==0)
__device__ __align__(16) uint4 g_TP4[NINT * 16];
__device__ __align__(16) uint4 g_TS4[NINT * 16];
__device__ float g_W[NT + 1];                  // weight(t) table, t in [0,2]
__device__ __align__(16) uint8_t g_M[MENT];    // m(half_bits(x)) interval table
__device__ int g_done_cnt;                     // setup-pieces completed (reset per launch)
__device__ int g_fin_cnt;                      // blocks finished (reset per launch)

// ---------------------------------------------------------------------------
// Helpers
// ---------------------------------------------------------------------------
__device__ __forceinline__ unsigned hash_id(int id) {
    return ((unsigned)id * 2654435761u) >> 22;  // 10 bits -> [0,1024)
}

// Single 1024-slot table; counts packed (src in lo16, dst in hi16).
__device__ __forceinline__ void hash_insert(int* keys, unsigned* cnts,
                                            int id, unsigned inc) {
    if (id == 0) return;
    unsigned slot = hash_id(id) & 1023u;
    while (true) {
        int prev = atomicCAS(&keys[slot], 0, id);
        if (prev == 0 || prev == id) { atomicAdd(&cnts[slot], inc); break; }
        slot = (slot + 1) & 1023u;
    }
}

__device__ __forceinline__ unsigned hash_lookup(const int* keys, const unsigned* cnts,
                                                int id) {
    if (id == 0) return 0u;
    unsigned slot = hash_id(id) & 1023u;
    while (true) {
        int k = keys[slot];
        if (k == id) return cnts[slot];
        if (k == 0) return 0u;
        slot = (slot + 1) & 1023u;
    }
}

__device__ __forceinline__ float weight_lookup(float t) {
    float u = t * ((float)NT * 0.5f);
    u = fminf(fmaxf(u, 0.0f), (float)NT - 0.001f);
    int i0 = (int)u;
    float f = u - (float)i0;
    float a  = __ldg(&g_W[i0]);
    float bb = __ldg(&g_W[i0 + 1]);
    return fmaf(f, bb - a, a);
}

// Predicated global v4 load, zero fallback. cond!=0 => load; else {0,0,0,0}.
__device__ __forceinline__ uint4 ldg128_pred0(const uint4* addr, uint32_t cond) {
    uint4 r = make_uint4(0u, 0u, 0u, 0u);
    asm volatile(
        "{\n\t"
        ".reg .pred p;\n\t"
        "setp.ne.u32 p, %4, 0;\n\t"
        "@p ld.global.nc.v4.u32 {%0, %1, %2, %3}, [%5];\n\t"
        "}"
        : "+r"(r.x), "+r"(r.y), "+r"(r.z), "+r"(r.w)
        : "r"(cond), "l"(addr));
    return r;
}

__device__ __forceinline__ __half2 h2(uint32_t u) { return *(const __half2*)&u; }

// Compute sorted relu thresholds into sTs (ascending, INF padded). Block-wide.
__device__ __forceinline__ void build_sorted_thresholds(
    const float* __restrict__ w1, const float* __restrict__ b1,
    float* sTin, float* sTs, int tid) {
    if (tid < NTHR) {
        float w = w1[tid], b = b1[tid];
        bool crossing = (w > 0.0f && b < 0.0f) || (w < 0.0f && b > 0.0f);
        sTin[tid] = crossing ? (-b / w) : CUDART_INF_F;
    }
    __syncthreads();
    if (tid < NTHR) {
        float t = sTin[tid];
        int rank = 0;
        #pragma unroll
        for (int j = 0; j < NTHR; ++j) {
            float tj = sTin[j];
            rank += (tj < t) || (tj == t && j < tid);
        }
        sTs[rank] = t;
    }
    __syncthreads();
}

// ---------------------------------------------------------------------------
// Single fused kernel. Block b handles batch row b.
// Blocks 0..NSETUP-1 additionally build one setup piece first, then publish
// via g_done_cnt. All blocks: hash phase (table-independent, overlaps setup),
// spin-gate on g_done_cnt, then weight/m lookups + Phase B epilogue.
// Last finishing block resets the counters for the next graph replay.
// ---------------------------------------------------------------------------
__global__ __launch_bounds__(LL, 8) void tni_fused_kernel(
    const int*   __restrict__ src_ids,
    const int*   __restrict__ dst_ids,
    const float* __restrict__ src_times,
    const float* __restrict__ dst_times,
    const float* __restrict__ node_times,
    const float* __restrict__ w_time,
    const float* __restrict__ b_time,
    const float* __restrict__ w_ts,
    const float* __restrict__ b_ts,
    const float* __restrict__ w1,
    const float* __restrict__ b1,
    const float* __restrict__ w2,
    const float* __restrict__ b2,
    float*       __restrict__ out)
{
    __shared__ __align__(16) int sHash[2048];   // setup scratch, then keys[1024]|cnts[1024]

    const int blk = blockIdx.x;
    const int tid = threadIdx.x;
    float* sf = (float*)sHash;                  // setup scratch overlay (<= 1280 floats)

    // ===================== setup pieces (blocks 0..NSETUP-1) ================
    if (blk < NINT) {
        // --- UV row m = blk ---
        float* sw1  = sf;        float* sb1 = sf + 64;
        float* sTin = sf + 128;  float* sTs = sf + 192;
        float* sb2v = sf + 256;
        float* spU  = sf + 320;  float* spV = sf + 576;  float* spV0 = sf + 832;
        float* sU   = sf + 1088; float* sV  = sf + 1152; float* sV0  = sf + 1216;

        if (tid < NTHR) { sw1[tid] = w1[tid]; sb1[tid] = b1[tid]; }
        if (tid < DD)   sb2v[tid] = b2[tid];
        __syncthreads();
        build_sorted_thresholds(w1, b1, sTin, sTs, tid);

        const int m = blk;
        float lo = (m == 0)        ? 0.0f         : sTs[m - 1];
        float hi = (m == NINT - 1) ? CUDART_INF_F : sTs[m];
        float mid;
        if (!isfinite(lo))      mid = 1.0f;
        else if (!isfinite(hi)) mid = lo * 2.0f + 1.0f;
        else                    mid = 0.5f * (lo + hi);

        const int j = tid & 63;
        const int q = tid >> 6;
        float U = 0.0f, V = 0.0f, V0 = 0.0f;
        #pragma unroll 4
        for (int k2 = q * 16; k2 < q * 16 + 16; ++k2) {
            float w = sw1[k2], bb = sb1[k2];
            float w2v = w2[k2 * DD + j];
            if (fmaf(mid, w, bb) > 0.0f) {
                U = fmaf(w, w2v, U);
                V = fmaf(bb, w2v, V);
            }
            if (bb > 0.0f) V0 = fmaf(bb, w2v, V0);
        }
        spU[q * DD + j] = U; spV[q * DD + j] = V; spV0[q * DD + j] = V0;
        __syncthreads();
        if (tid < DD) {
            sU[tid]  = spU[tid]  + spU[DD + tid]  + spU[2 * DD + tid]  + spU[3 * DD + tid];
            sV[tid]  = spV[tid]  + spV[DD + tid]  + spV[2 * DD + tid]  + spV[3 * DD + tid];
            sV0[tid] = spV0[tid] + spV0[DD + tid] + spV0[2 * DD + tid] + spV0[3 * DD + tid];
        }
        __syncthreads();
        if (tid < 16) {
            const int l = tid;
            const int j0 = 4 * l;
            __half2 U01 = __floats2half2_rn(sU[j0],     sU[j0 + 1]);
            __half2 U23 = __floats2half2_rn(sU[j0 + 2], sU[j0 + 3]);
            __half2 VP01 = __floats2half2_rn(sV[j0]     + sV0[j0]     + 2.0f * sb2v[j0],
                                             sV[j0 + 1] + sV0[j0 + 1] + 2.0f * sb2v[j0 + 1]);
            __half2 VP23 = __floats2half2_rn(sV[j0 + 2] + sV0[j0 + 2] + 2.0f * sb2v[j0 + 2],
                                             sV[j0 + 3] + sV0[j0 + 3] + 2.0f * sb2v[j0 + 3]);
            __half2 VS01 = __floats2half2_rn(sV[j0]     - sV0[j0],
                                             sV[j0 + 1] - sV0[j0 + 1]);
            __half2 VS23 = __floats2half2_rn(sV[j0 + 2] - sV0[j0 + 2],
                                             sV[j0 + 3] - sV0[j0 + 3]);
            g_TP4[m * 16 + l] = make_uint4(*(const uint32_t*)&U01, *(const uint32_t*)&U23,
                                           *(const uint32_t*)&VP01, *(const uint32_t*)&VP23);
            g_TS4[m * 16 + l] = make_uint4(*(const uint32_t*)&U01, *(const uint32_t*)&U23,
                                           *(const uint32_t*)&VS01, *(const uint32_t*)&VS23);
        }
        __threadfence();
        __syncthreads();
        if (tid == 0) atomicAdd(&g_done_cnt, 1);
    } else if (blk < NINT + 5) {
        // --- weight table chunk ---
        float* swt = sf; float* sbt = sf + TDIM; float* sws = sf + 2 * TDIM;
        if (tid < TDIM) {
            swt[tid] = w_time[tid];
            sbt[tid] = b_time[tid];
            sws[tid] = w_ts[tid];
        }
        __syncthreads();
        int g = (blk - NINT) * 256 + tid;
        if (g <= NT) {
            float t = (float)g * (2.0f / (float)NT);
            float acc = b_ts[0];
            #pragma unroll 4
            for (int k = 0; k < TDIM; ++k)
                acc = fmaf(__cosf(fmaf(t, swt[k], sbt[k])), sws[k], acc);
            g_W[g] = 1.0f / (1.0f + __expf(-acc));
        }
        __threadfence();
        __syncthreads();
        if (tid == 0) atomicAdd(&g_done_cnt, 1);
    } else if (blk < NSETUP) {
        // --- m-table chunk: 1024 entries, 4 per thread (x < 256 => <= 0x5C00) ---
        float* sTin = sf; float* sTs = sf + 64;
        build_sorted_thresholds(w1, b1, sTin, sTs, tid);
        const int base = (blk - (NINT + 5)) * 1024 + tid * 4;
        uint32_t packed = 0;
        #pragma unroll
        for (int e = 0; e < 4; ++e) {
            const unsigned short us = (unsigned short)(base + e);
            const float v = __half2float(__ushort_as_half(us));
            int m = 0;
            #pragma unroll
            for (int s = 32; s >= 1; s >>= 1)
                if (sTs[m + s - 1] < v) m += s;
            if (m < NTHR && sTs[m] < v) ++m;
            if (m > NTHR) m = NTHR;
            packed |= ((uint32_t)m & 255u) << (8 * e);
        }
        ((uint32_t*)g_M)[base >> 2] = packed;
        __threadfence();
        __syncthreads();
        if (tid == 0) atomicAdd(&g_done_cnt, 1);
    }
    __syncthreads();   // setup scratch dead; safe to overlay hash

    // ===================== Phase A: hash histogram (table-independent) ======
    const int b = blk;
    const int i = tid;

    #pragma unroll
    for (int t = 0; t < 2; ++t)
        ((int4*)sHash)[i + t * LL] = make_int4(0, 0, 0, 0);

    const int sid = src_ids[b * LL + i];
    const int did = dst_ids[b * LL + i];
    __syncthreads();

    int*      keys = sHash;
    unsigned* cnts = (unsigned*)(sHash + 1024);
    hash_insert(keys, cnts, sid, 1u);          // src occurrence -> lo16
    hash_insert(keys, cnts, did, 0x10000u);    // dst occurrence -> hi16
    __syncthreads();

    const unsigned pS = hash_lookup(keys, cnts, sid);  // {csd:hi, css:lo}
    const unsigned pD = hash_lookup(keys, cnts, did);  // {cdd:hi, cds:lo}
    const int css = (int)(pS & 0xFFFFu);
    const int csd = (int)(pS >> 16);
    const int cds = (int)(pD & 0xFFFFu);
    const int cdd = (int)(pD >> 16);

    const float nt  = node_times[b];
    const float ts_ = nt - src_times[b * LL + i];
    const float td_ = nt - dst_times[b * LL + i];

    // ===================== spin-gate: wait for all setup pieces =============
    if (i == 0) {
        while (atomicAdd(&g_done_cnt, 0) < NSETUP) __nanosleep(64);
    }
    __syncthreads();
    __threadfence();

    // ===================== weights, x, m ====================================
    const float ws = weight_lookup(ts_);
    const float wd = weight_lookup(td_);

    __half2 hxs = __floats2half2_rn((float)css * ws, (float)csd * ws);
    __half2 hxd = __floats2half2_rn((float)cds * wd, (float)cdd * wd);
    const uint32_t pk0 = *(const uint32_t*)&hxs;
    const uint32_t pk1 = *(const uint32_t*)&hxd;

    const uint32_t m_ss = __ldg(&g_M[pk0 & 0xFFFFu]);
    const uint32_t m_sd = __ldg(&g_M[pk0 >> 16]);
    const uint32_t m_ds = __ldg(&g_M[pk1 & 0xFFFFu]);
    const uint32_t m_dd = __ldg(&g_M[pk1 >> 16]);
    const uint32_t pkm = m_ss | (m_sd << 8) | (m_ds << 16) | (m_dd << 24);

    // ===================== Phase B: per-warp epilogue =======================
    const int wid  = i >> 5;
    const int lane = i & 31;
    const int lsub = lane & 15;
    const int hsel = lane >> 4;

    const uint4* __restrict__ TP = g_TP4;
    const uint4* __restrict__ TS = g_TS4;
    const size_t dst_off = (size_t)BB * LL * DD;
    const size_t brow = (size_t)b * LL;

    #pragma unroll 2
    for (int p0 = 0; p0 < 16; ++p0) {
        const int src = (p0 << 1) + hsel;
        const uint32_t qx = __shfl_sync(0xFFFFFFFFu, pk0, src);
        const uint32_t qy = __shfl_sync(0xFFFFFFFFu, pk1, src);
        const uint32_t mm = __shfl_sync(0xFFFFFFFFu, pkm, src);

        const uint32_t mss = mm & 255u;
        const uint32_t msd = (mm >> 8) & 255u;
        const uint32_t mds = (mm >> 16) & 255u;
        const uint32_t mdd = mm >> 24;

        const uint4 Ap = __ldg(&TP[mss * 16 + lsub]);
        const uint4 Dp = __ldg(&TP[mdd * 16 + lsub]);
        const uint4 Bs = ldg128_pred0(&TS[msd * 16 + lsub], qx & 0xFFFF0000u);
        const uint4 Cs = ldg128_pred0(&TS[mds * 16 + lsub], qy & 0x0000FFFFu);

        const __half2 hs = h2(qx);
        const __half2 hd = h2(qy);
        const __half2 xss2 = __low2half2(hs),  xsd2 = __high2half2(hs);
        const __half2 xds2 = __low2half2(hd),  xdd2 = __high2half2(hd);

        const __half2 rs01 = __hadd2(__hfma2(xss2, h2(Ap.x), h2(Ap.z)),
                                     __hfma2(xsd2, h2(Bs.x), h2(Bs.z)));
        const __half2 rs23 = __hadd2(__hfma2(xss2, h2(Ap.y), h2(Ap.w)),
                                     __hfma2(xsd2, h2(Bs.y), h2(Bs.w)));
        const __half2 rd01 = __hadd2(__hfma2(xdd2, h2(Dp.x), h2(Dp.z)),
                                     __hfma2(xds2, h2(Cs.x), h2(Cs.z)));
        const __half2 rd23 = __hadd2(__hfma2(xdd2, h2(Dp.y), h2(Dp.w)),
                                     __hfma2(xds2, h2(Cs.y), h2(Cs.w)));

        const float2 s0 = __half22float2(rs01);
        const float2 s1 = __half22float2(rs23);
        const float2 d0 = __half22float2(rd01);
        const float2 d1 = __half22float2(rd23);

        const int p = (wid << 5) + (p0 << 1) + hsel;
        const size_t rowbase = (brow + p) * DD + 4 * lsub;
        *(float4*)(out + rowbase)           = make_float4(s0.x, s0.y, s1.x, s1.y);
        *(float4*)(out + dst_off + rowbase) = make_float4(d0.x, d0.y, d1.x, d1.y);
    }

    // ===================== epilogue: reset counters for next replay =========
    __syncthreads();
    if (tid == 0) {
        int done = atomicAdd(&g_fin_cnt, 1);
        if (done == BB - 1) {
            g_done_cnt = 0;
            g_fin_cnt  = 0;
            __threadfence();
        }
    }
}

// ---------------------------------------------------------------------------
// Inputs: 0 src_ids, 1 dst_ids, 2 src_times, 3 dst_times, 4 node_times,
// 5 num_nodes (unused), 6 w_time, 7 b_time, 8 w_ts, 9 b_ts, 10 w1, 11 b1,
// 12 w2, 13 b2.  Output: [src_feats (B,L,D); dst_feats (B,L,D)].
// ---------------------------------------------------------------------------
extern "C" void kernel_launch(void* const* d_in, const int* in_sizes, int n_in,
                              void* d_out, int out_size) {
    const int*   src_ids    = (const int*)  d_in[0];
    const int*   dst_ids    = (const int*)  d_in[1];
    const float* src_times  = (const float*)d_in[2];
    const float* dst_times  = (const float*)d_in[3];
    const float* node_times = (const float*)d_in[4];
    const float* w_time     = (const float*)d_in[6];
    const float* b_time     = (const float*)d_in[7];
    const float* w_ts       = (const float*)d_in[8];
    const float* b_ts       = (const float*)d_in[9];
    const float* w1         = (const float*)d_in[10];
    const float* b1         = (const float*)d_in[11];
    const float* w2         = (const float*)d_in[12];
    const float* b2         = (const float*)d_in[13];
    float*       out        = (float*)d_out;

    tni_fused_kernel<<<BB, LL>>>(src_ids, dst_ids, src_times, dst_times,
                                 node_times, w_time, b_time, w_ts, b_ts,
                                 w1, b1, w2, b2, out);
}

// round 13
// speedup vs baseline: 1.2878x; 1.2878x over previous
#include <cuda_runtime.h>
#include <cuda_fp16.h>
#include <math_constants.h>
#include <cstdint>

#define BB 1024
#define LL 256
#define DD 64
#define TDIM 100
#define NTHR 64
#define NINT 65
#define NT 1024          // weight-table intervals (table has NT+1 entries)
#define MBLK 24          // m-table builder blocks (24 x 1024 = 24576 entries)
#define MENT (MBLK * 1024)   // covers half patterns up to 384.0 (x < 256.0 always)
#define NSETUP (NINT + 5 + MBLK)   // 94 setup blocks
#define NWM (5 + MBLK)   // weight + m-table pieces (29)

// Scratch in __device__ globals (no allocations allowed).
// Row m = 16 uint4 per plane, each {U01,U23,V01,V23} (half2 words):
//   P: V'_m = V_m + V0 + 2*b2   (always-loaded operand)
//   S: V'_m = V_m - V0          (predicated; row contribution exactly 0 when x==0)
__device__ __align__(16) uint4 g_TP4[NINT * 16];
__device__ __align__(16) uint4 g_TS4[NINT * 16];
__device__ float g_W[NT + 1];                  // weight(t) table, t in [0,2]
__device__ __align__(16) uint8_t g_M[MENT];    // m(half_bits(x)) interval table
__device__ int g_cnt_uv;                       // UV pieces done (reset per launch)
__device__ int g_cnt_wm;                       // W+M pieces done (reset per launch)
__device__ int g_fin_cnt;                      // blocks finished (reset per launch)

// ---------------------------------------------------------------------------
// Helpers (R11 split-table hash: two 512-slot tables, halves concurrent-insert
// density per cluster — the merged R12 table caused CAS-retry storms)
// ---------------------------------------------------------------------------
__device__ __forceinline__ unsigned hash_id(int id) {
    return ((unsigned)id * 2654435761u) >> 23;  // 9 bits -> [0,512)
}

__device__ __forceinline__ void hash_insert(int* keys, int* cnts, int base, int id) {
    if (id == 0) return;
    unsigned slot = hash_id(id) & 511u;
    while (true) {
        int prev = atomicCAS(&keys[base + slot], 0, id);
        if (prev == 0 || prev == id) { atomicAdd(&cnts[base + slot], 1); break; }
        slot = (slot + 1) & 511u;
    }
}

__device__ __forceinline__ int hash_lookup(const int* keys, const int* cnts,
                                           int base, int id) {
    if (id == 0) return 0;
    unsigned slot = hash_id(id) & 511u;
    while (true) {
        int k = keys[base + slot];
        if (k == id) return cnts[base + slot];
        if (k == 0) return 0;
        slot = (slot + 1) & 511u;
    }
}

__device__ __forceinline__ float weight_lookup(float t) {
    float u = t * ((float)NT * 0.5f);
    u = fminf(fmaxf(u, 0.0f), (float)NT - 0.001f);
    int i0 = (int)u;
    float f = u - (float)i0;
    float a  = __ldg(&g_W[i0]);
    float bb = __ldg(&g_W[i0 + 1]);
    return fmaf(f, bb - a, a);
}

// Predicated global v4 load, zero fallback. cond!=0 => load; else {0,0,0,0}.
__device__ __forceinline__ uint4 ldg128_pred0(const uint4* addr, uint32_t cond) {
    uint4 r = make_uint4(0u, 0u, 0u, 0u);
    asm volatile(
        "{\n\t"
        ".reg .pred p;\n\t"
        "setp.ne.u32 p, %4, 0;\n\t"
        "@p ld.global.nc.v4.u32 {%0, %1, %2, %3}, [%5];\n\t"
        "}"
        : "+r"(r.x), "+r"(r.y), "+r"(r.z), "+r"(r.w)
        : "r"(cond), "l"(addr));
    return r;
}

__device__ __forceinline__ __half2 h2(uint32_t u) { return *(const __half2*)&u; }

// Compute sorted relu thresholds into sTs (ascending, INF padded). Block-wide.
__device__ __forceinline__ void build_sorted_thresholds(
    const float* __restrict__ w1, const float* __restrict__ b1,
    float* sTin, float* sTs, int tid) {
    if (tid < NTHR) {
        float w = w1[tid], b = b1[tid];
        bool crossing = (w > 0.0f && b < 0.0f) || (w < 0.0f && b > 0.0f);
        sTin[tid] = crossing ? (-b / w) : CUDART_INF_F;
    }
    __syncthreads();
    if (tid < NTHR) {
        float t = sTin[tid];
        int rank = 0;
        #pragma unroll
        for (int j = 0; j < NTHR; ++j) {
            float tj = sTin[j];
            rank += (tj < t) || (tj == t && j < tid);
        }
        sTs[rank] = t;
    }
    __syncthreads();
}

// ---------------------------------------------------------------------------
// Single fused kernel. Block b handles batch row b.
// Blocks 0..NSETUP-1 additionally build one setup piece first (UV rows bump
// g_cnt_uv; W and M pieces bump g_cnt_wm). All blocks: hash phase (overlaps
// setup), gate on g_cnt_wm before weight/m lookups, gate on g_cnt_uv before
// Phase B. Last finishing block resets counters for the next graph replay.
// ---------------------------------------------------------------------------
__global__ __launch_bounds__(LL, 8) void tni_fused_kernel(
    const int*   __restrict__ src_ids,
    const int*   __restrict__ dst_ids,
    const float* __restrict__ src_times,
    const float* __restrict__ dst_times,
    const float* __restrict__ node_times,
    const float* __restrict__ w_time,
    const float* __restrict__ b_time,
    const float* __restrict__ w_ts,
    const float* __restrict__ b_ts,
    const float* __restrict__ w1,
    const float* __restrict__ b1,
    const float* __restrict__ w2,
    const float* __restrict__ b2,
    float*       __restrict__ out)
{
    __shared__ __align__(16) int sHash[2048];   // setup scratch, then keys|counts

    const int blk = blockIdx.x;
    const int tid = threadIdx.x;
    float* sf = (float*)sHash;                  // setup scratch overlay (<= 1280 floats)

    // ===================== setup pieces (blocks 0..NSETUP-1) ================
    if (blk < NINT) {
        // --- UV row m = blk ---
        float* sw1  = sf;        float* sb1 = sf + 64;
        float* sTin = sf + 128;  float* sTs = sf + 192;
        float* sb2v = sf + 256;
        float* spU  = sf + 320;  float* spV = sf + 576;  float* spV0 = sf + 832;
        float* sU   = sf + 1088; float* sV  = sf + 1152; float* sV0  = sf + 1216;

        if (tid < NTHR) { sw1[tid] = w1[tid]; sb1[tid] = b1[tid]; }
        if (tid < DD)   sb2v[tid] = b2[tid];
        __syncthreads();
        build_sorted_thresholds(w1, b1, sTin, sTs, tid);

        const int m = blk;
        float lo = (m == 0)        ? 0.0f         : sTs[m - 1];
        float hi = (m == NINT - 1) ? CUDART_INF_F : sTs[m];
        float mid;
        if (!isfinite(lo))      mid = 1.0f;
        else if (!isfinite(hi)) mid = lo * 2.0f + 1.0f;
        else                    mid = 0.5f * (lo + hi);

        const int j = tid & 63;
        const int q = tid >> 6;
        float U = 0.0f, V = 0.0f, V0 = 0.0f;
        #pragma unroll 4
        for (int k2 = q * 16; k2 < q * 16 + 16; ++k2) {
            float w = sw1[k2], bb = sb1[k2];
            float w2v = w2[k2 * DD + j];
            if (fmaf(mid, w, bb) > 0.0f) {
                U = fmaf(w, w2v, U);
                V = fmaf(bb, w2v, V);
            }
            if (bb > 0.0f) V0 = fmaf(bb, w2v, V0);
        }
        spU[q * DD + j] = U; spV[q * DD + j] = V; spV0[q * DD + j] = V0;
        __syncthreads();
        if (tid < DD) {
            sU[tid]  = spU[tid]  + spU[DD + tid]  + spU[2 * DD + tid]  + spU[3 * DD + tid];
            sV[tid]  = spV[tid]  + spV[DD + tid]  + spV[2 * DD + tid]  + spV[3 * DD + tid];
            sV0[tid] = spV0[tid] + spV0[DD + tid] + spV0[2 * DD + tid] + spV0[3 * DD + tid];
        }
        __syncthreads();
        if (tid < 16) {
            const int l = tid;
            const int j0 = 4 * l;
            __half2 U01 = __floats2half2_rn(sU[j0],     sU[j0 + 1]);
            __half2 U23 = __floats2half2_rn(sU[j0 + 2], sU[j0 + 3]);
            __half2 VP01 = __floats2half2_rn(sV[j0]     + sV0[j0]     + 2.0f * sb2v[j0],
                                             sV[j0 + 1] + sV0[j0 + 1] + 2.0f * sb2v[j0 + 1]);
            __half2 VP23 = __floats2half2_rn(sV[j0 + 2] + sV0[j0 + 2] + 2.0f * sb2v[j0 + 2],
                                             sV[j0 + 3] + sV0[j0 + 3] + 2.0f * sb2v[j0 + 3]);
            __half2 VS01 = __floats2half2_rn(sV[j0]     - sV0[j0],
                                             sV[j0 + 1] - sV0[j0 + 1]);
            __half2 VS23 = __floats2half2_rn(sV[j0 + 2] - sV0[j0 + 2],
                                             sV[j0 + 3] - sV0[j0 + 3]);
            g_TP4[m * 16 + l] = make_uint4(*(const uint32_t*)&U01, *(const uint32_t*)&U23,
                                           *(const uint32_t*)&VP01, *(const uint32_t*)&VP23);
            g_TS4[m * 16 + l] = make_uint4(*(const uint32_t*)&U01, *(const uint32_t*)&U23,
                                           *(const uint32_t*)&VS01, *(const uint32_t*)&VS23);
        }
        __threadfence();
        __syncthreads();
        if (tid == 0) atomicAdd(&g_cnt_uv, 1);
    } else if (blk < NINT + 5) {
        // --- weight table chunk ---
        float* swt = sf; float* sbt = sf + TDIM; float* sws = sf + 2 * TDIM;
        if (tid < TDIM) {
            swt[tid] = w_time[tid];
            sbt[tid] = b_time[tid];
            sws[tid] = w_ts[tid];
        }
        __syncthreads();
        int g = (blk - NINT) * 256 + tid;
        if (g <= NT) {
            float t = (float)g * (2.0f / (float)NT);
            float acc = b_ts[0];
            #pragma unroll 4
            for (int k = 0; k < TDIM; ++k)
                acc = fmaf(__cosf(fmaf(t, swt[k], sbt[k])), sws[k], acc);
            g_W[g] = 1.0f / (1.0f + __expf(-acc));
        }
        __threadfence();
        __syncthreads();
        if (tid == 0) atomicAdd(&g_cnt_wm, 1);
    } else if (blk < NSETUP) {
        // --- m-table chunk: 1024 entries, 4 per thread (x < 256 => <= 0x5C00) ---
        float* sTin = sf; float* sTs = sf + 64;
        build_sorted_thresholds(w1, b1, sTin, sTs, tid);
        const int base = (blk - (NINT + 5)) * 1024 + tid * 4;
        uint32_t packed = 0;
        #pragma unroll
        for (int e = 0; e < 4; ++e) {
            const unsigned short us = (unsigned short)(base + e);
            const float v = __half2float(__ushort_as_half(us));
            int m = 0;
            #pragma unroll
            for (int s = 32; s >= 1; s >>= 1)
                if (sTs[m + s - 1] < v) m += s;
            if (m < NTHR && sTs[m] < v) ++m;
            if (m > NTHR) m = NTHR;
            packed |= ((uint32_t)m & 255u) << (8 * e);
        }
        ((uint32_t*)g_M)[base >> 2] = packed;
        __threadfence();
        __syncthreads();
        if (tid == 0) atomicAdd(&g_cnt_wm, 1);
    }
    __syncthreads();   // setup scratch dead; safe to overlay hash

    // ===================== Phase A: hash histogram (table-independent) ======
    const int b = blk;
    const int i = tid;

    #pragma unroll
    for (int t = 0; t < 2; ++t)
        ((int4*)sHash)[i + t * LL] = make_int4(0, 0, 0, 0);

    const int sid = src_ids[b * LL + i];
    const int did = dst_ids[b * LL + i];
    __syncthreads();

    int* keys = sHash;
    int* cnts = sHash + 1024;
    hash_insert(keys, cnts, 0,   sid);
    hash_insert(keys, cnts, 512, did);
    __syncthreads();

    const int css = hash_lookup(keys, cnts, 0,   sid);
    const int csd = hash_lookup(keys, cnts, 512, sid);
    const int cds = hash_lookup(keys, cnts, 0,   did);
    const int cdd = hash_lookup(keys, cnts, 512, did);

    const float nt  = node_times[b];
    const float ts_ = nt - src_times[b * LL + i];
    const float td_ = nt - dst_times[b * LL + i];

    // ===================== gate 1: weight + m tables ready ==================
    if (i == 0) {
        while (atomicAdd(&g_cnt_wm, 0) < NWM) __nanosleep(64);
    }
    __syncthreads();
    __threadfence();

    // ===================== weights, x, m ====================================
    const float ws = weight_lookup(ts_);
    const float wd = weight_lookup(td_);

    __half2 hxs = __floats2half2_rn((float)css * ws, (float)csd * ws);
    __half2 hxd = __floats2half2_rn((float)cds * wd, (float)cdd * wd);
    const uint32_t pk0 = *(const uint32_t*)&hxs;
    const uint32_t pk1 = *(const uint32_t*)&hxd;

    const uint32_t m_ss = __ldg(&g_M[pk0 & 0xFFFFu]);
    const uint32_t m_sd = __ldg(&g_M[pk0 >> 16]);
    const uint32_t m_ds = __ldg(&g_M[pk1 & 0xFFFFu]);
    const uint32_t m_dd = __ldg(&g_M[pk1 >> 16]);
    const uint32_t pkm = m_ss | (m_sd << 8) | (m_ds << 16) | (m_dd << 24);

    // ===================== gate 2: UV tables ready ==========================
    if (i == 0) {
        while (atomicAdd(&g_cnt_uv, 0) < NINT) __nanosleep(64);
    }
    __syncthreads();
    __threadfence();

    // ===================== Phase B: per-warp epilogue =======================
    const int wid  = i >> 5;
    const int lane = i & 31;
    const int lsub = lane & 15;
    const int hsel = lane >> 4;

    const uint4* __restrict__ TP = g_TP4;
    const uint4* __restrict__ TS = g_TS4;
    const size_t dst_off = (size_t)BB * LL * DD;
    const size_t brow = (size_t)b * LL;

    #pragma unroll 2
    for (int p0 = 0; p0 < 16; ++p0) {
        const int src = (p0 << 1) + hsel;
        const uint32_t qx = __shfl_sync(0xFFFFFFFFu, pk0, src);
        const uint32_t qy = __shfl_sync(0xFFFFFFFFu, pk1, src);
        const uint32_t mm = __shfl_sync(0xFFFFFFFFu, pkm, src);

        const uint32_t mss = mm & 255u;
        const uint32_t msd = (mm >> 8) & 255u;
        const uint32_t mds = (mm >> 16) & 255u;
        const uint32_t mdd = mm >> 24;

        const uint4 Ap = __ldg(&TP[mss * 16 + lsub]);
        const uint4 Dp = __ldg(&TP[mdd * 16 + lsub]);
        const uint4 Bs = ldg128_pred0(&TS[msd * 16 + lsub], qx & 0xFFFF0000u);
        const uint4 Cs = ldg128_pred0(&TS[mds * 16 + lsub], qy & 0x0000FFFFu);

        const __half2 hs = h2(qx);
        const __half2 hd = h2(qy);
        const __half2 xss2 = __low2half2(hs),  xsd2 = __high2half2(hs);
        const __half2 xds2 = __low2half2(hd),  xdd2 = __high2half2(hd);

        const __half2 rs01 = __hadd2(__hfma2(xss2, h2(Ap.x), h2(Ap.z)),
                                     __hfma2(xsd2, h2(Bs.x), h2(Bs.z)));
        const __half2 rs23 = __hadd2(__hfma2(xss2, h2(Ap.y), h2(Ap.w)),
                                     __hfma2(xsd2, h2(Bs.y), h2(Bs.w)));
        const __half2 rd01 = __hadd2(__hfma2(xdd2, h2(Dp.x), h2(Dp.z)),
                                     __hfma2(xds2, h2(Cs.x), h2(Cs.z)));
        const __half2 rd23 = __hadd2(__hfma2(xdd2, h2(Dp.y), h2(Dp.w)),
                                     __hfma2(xds2, h2(Cs.y), h2(Cs.w)));

        const float2 s0 = __half22float2(rs01);
        const float2 s1 = __half22float2(rs23);
        const float2 d0 = __half22float2(rd01);
        const float2 d1 = __half22float2(rd23);

        const int p = (wid << 5) + (p0 << 1) + hsel;
        const size_t rowbase = (brow + p) * DD + 4 * lsub;
        *(float4*)(out + rowbase)           = make_float4(s0.x, s0.y, s1.x, s1.y);
        *(float4*)(out + dst_off + rowbase) = make_float4(d0.x, d0.y, d1.x, d1.y);
    }

    // ===================== epilogue: reset counters for next replay =========
    __syncthreads();
    if (tid == 0) {
        int done = atomicAdd(&g_fin_cnt, 1);
        if (done == BB - 1) {
            g_cnt_uv  = 0;
            g_cnt_wm  = 0;
            g_fin_cnt = 0;
            __threadfence();
        }
    }
}

// ---------------------------------------------------------------------------
// Inputs: 0 src_ids, 1 dst_ids, 2 src_times, 3 dst_times, 4 node_times,
// 5 num_nodes (unused), 6 w_time, 7 b_time, 8 w_ts, 9 b_ts, 10 w1, 11 b1,
// 12 w2, 13 b2.  Output: [src_feats (B,L,D); dst_feats (B,L,D)].
// ---------------------------------------------------------------------------
extern "C" void kernel_launch(void* const* d_in, const int* in_sizes, int n_in,
                              void* d_out, int out_size) {
    const int*   src_ids    = (const int*)  d_in[0];
    const int*   dst_ids    = (const int*)  d_in[1];
    const float* src_times  = (const float*)d_in[2];
    const float* dst_times  = (const float*)d_in[3];
    const float* node_times = (const float*)d_in[4];
    const float* w_time     = (const float*)d_in[6];
    const float* b_time     = (const float*)d_in[7];
    const float* w_ts       = (const float*)d_in[8];
    const float* b_ts       = (const float*)d_in[9];
    const float* w1         = (const float*)d_in[10];
    const float* b1         = (const float*)d_in[11];
    const float* w2         = (const float*)d_in[12];
    const float* b2         = (const float*)d_in[13];
    float*       out        = (float*)d_out;

    tni_fused_kernel<<<BB, LL>>>(src_ids, dst_ids, src_times, dst_times,
                                 node_times, w_time, b_time, w_ts, b_ts,
                                 w1, b1, w2, b2, out);
}

// round 16
// speedup vs baseline: 1.3162x; 1.0221x over previous
#include <cuda_runtime.h>
#include <cuda_fp16.h>
#include <math_constants.h>
#include <cstdint>

#define BB 1024
#define LL 256
#define DD 64
#define TDIM 100
#define NTHR 64
#define NINT 65
#define NT 1024          // weight-table intervals (table has NT+1 entries)
#define MBLK 24          // m-table builder blocks (24 x 1024 = 24576 entries)
#define MENT (MBLK * 1024)   // covers half patterns up to 384.0 (x < 256.0 always)
#define NSETUP (NINT + 5 + MBLK)   // 94 setup blocks

// Scratch in __device__ globals (no allocations allowed).
// Row m = 16 uint4 per plane, each {U01,U23,V01,V23} (half2 words):
//   P: V'_m = V_m + V0 + 2*b2   (always-loaded operand)
//   S: V'_m = V_m - V0          (predicated; row contribution exactly 0 when x==0)
__device__ __align__(16) uint4 g_TP4[NINT * 16];
__device__ __align__(16) uint4 g_TS4[NINT * 16];
__device__ float g_W[NT + 1];                  // weight(t) table, t in [0,2]
__device__ __align__(16) uint8_t g_M[MENT];    // m(half_bits(x)) interval table
__device__ int g_done_cnt;                     // setup pieces done (reset per launch)
__device__ int g_fin_cnt;                      // blocks finished (reset per launch)

// ---------------------------------------------------------------------------
// Helpers (split-table hash: two 512-slot tables — low concurrent-insert
// density; the merged R12 table caused CAS-retry storms)
// ---------------------------------------------------------------------------
__device__ __forceinline__ unsigned hash_id(int id) {
    return ((unsigned)id * 2654435761u) >> 23;  // 9 bits -> [0,512)
}

// Insert id into table at base; returns ABSOLUTE slot index (or -1 for id==0).
// The slot is stable once claimed, so the caller can read cnts[slot] after the
// completion barrier — no second probe walk for the "own id, own table" count.
__device__ __forceinline__ int hash_insert(int* keys, int* cnts, int base, int id) {
    if (id == 0) return -1;
    unsigned slot = hash_id(id) & 511u;
    while (true) {
        int prev = atomicCAS(&keys[base + slot], 0, id);
        if (prev == 0 || prev == id) {
            atomicAdd(&cnts[base + slot], 1);
            return base + (int)slot;
        }
        slot = (slot + 1) & 511u;
    }
}

__device__ __forceinline__ int hash_lookup(const int* keys, const int* cnts,
                                           int base, int id) {
    if (id == 0) return 0;
    unsigned slot = hash_id(id) & 511u;
    while (true) {
        int k = keys[base + slot];
        if (k == id) return cnts[base + slot];
        if (k == 0) return 0;
        slot = (slot + 1) & 511u;
    }
}

__device__ __forceinline__ float weight_lookup(float t) {
    float u = t * ((float)NT * 0.5f);
    u = fminf(fmaxf(u, 0.0f), (float)NT - 0.001f);
    int i0 = (int)u;
    float f = u - (float)i0;
    float a  = __ldg(&g_W[i0]);
    float bb = __ldg(&g_W[i0 + 1]);
    return fmaf(f, bb - a, a);
}

// Predicated global v4 load, zero fallback. cond!=0 => load; else {0,0,0,0}.
__device__ __forceinline__ uint4 ldg128_pred0(const uint4* addr, uint32_t cond) {
    uint4 r = make_uint4(0u, 0u, 0u, 0u);
    asm volatile(
        "{\n\t"
        ".reg .pred p;\n\t"
        "setp.ne.u32 p, %4, 0;\n\t"
        "@p ld.global.nc.v4.u32 {%0, %1, %2, %3}, [%5];\n\t"
        "}"
        : "+r"(r.x), "+r"(r.y), "+r"(r.z), "+r"(r.w)
        : "r"(cond), "l"(addr));
    return r;
}

__device__ __forceinline__ __half2 h2(uint32_t u) { return *(const __half2*)&u; }

// Compute sorted relu thresholds into sTs (ascending, INF padded). Block-wide.
__device__ __forceinline__ void build_sorted_thresholds(
    const float* __restrict__ w1, const float* __restrict__ b1,
    float* sTin, float* sTs, int tid) {
    if (tid < NTHR) {
        float w = w1[tid], b = b1[tid];
        bool crossing = (w > 0.0f && b < 0.0f) || (w < 0.0f && b > 0.0f);
        sTin[tid] = crossing ? (-b / w) : CUDART_INF_F;
    }
    __syncthreads();
    if (tid < NTHR) {
        float t = sTin[tid];
        int rank = 0;
        #pragma unroll
        for (int j = 0; j < NTHR; ++j) {
            float tj = sTin[j];
            rank += (tj < t) || (tj == t && j < tid);
        }
        sTs[rank] = t;
    }
    __syncthreads();
}

// ---------------------------------------------------------------------------
// Single fused kernel. Block b handles batch row b.
// Blocks 0..NSETUP-1 additionally build one setup piece first, then publish
// via g_done_cnt. All blocks: hash phase (table-independent, overlaps setup),
// ONE spin-gate, then weight/m lookups + Phase B epilogue.
// Last finishing block resets the counters for the next graph replay.
// ---------------------------------------------------------------------------
__global__ __launch_bounds__(LL, 8) void tni_fused_kernel(
    const int*   __restrict__ src_ids,
    const int*   __restrict__ dst_ids,
    const float* __restrict__ src_times,
    const float* __restrict__ dst_times,
    const float* __restrict__ node_times,
    const float* __restrict__ w_time,
    const float* __restrict__ b_time,
    const float* __restrict__ w_ts,
    const float* __restrict__ b_ts,
    const float* __restrict__ w1,
    const float* __restrict__ b1,
    const float* __restrict__ w2,
    const float* __restrict__ b2,
    float*       __restrict__ out)
{
    __shared__ __align__(16) int sHash[2048];   // setup scratch, then keys|counts

    const int blk = blockIdx.x;
    const int tid = threadIdx.x;
    float* sf = (float*)sHash;                  // setup scratch overlay (<= 1280 floats)

    // ===================== setup pieces (blocks 0..NSETUP-1) ================
    if (blk < NINT) {
        // --- UV row m = blk ---
        float* sw1  = sf;        float* sb1 = sf + 64;
        float* sTin = sf + 128;  float* sTs = sf + 192;
        float* sb2v = sf + 256;
        float* spU  = sf + 320;  float* spV = sf + 576;  float* spV0 = sf + 832;
        float* sU   = sf + 1088; float* sV  = sf + 1152; float* sV0  = sf + 1216;

        if (tid < NTHR) { sw1[tid] = w1[tid]; sb1[tid] = b1[tid]; }
        if (tid < DD)   sb2v[tid] = b2[tid];
        __syncthreads();
        build_sorted_thresholds(w1, b1, sTin, sTs, tid);

        const int m = blk;
        float lo = (m == 0)        ? 0.0f         : sTs[m - 1];
        float hi = (m == NINT - 1) ? CUDART_INF_F : sTs[m];
        float mid;
        if (!isfinite(lo))      mid = 1.0f;
        else if (!isfinite(hi)) mid = lo * 2.0f + 1.0f;
        else                    mid = 0.5f * (lo + hi);

        const int j = tid & 63;
        const int q = tid >> 6;
        float U = 0.0f, V = 0.0f, V0 = 0.0f;
        #pragma unroll 4
        for (int k2 = q * 16; k2 < q * 16 + 16; ++k2) {
            float w = sw1[k2], bb = sb1[k2];
            float w2v = w2[k2 * DD + j];
            if (fmaf(mid, w, bb) > 0.0f) {
                U = fmaf(w, w2v, U);
                V = fmaf(bb, w2v, V);
            }
            if (bb > 0.0f) V0 = fmaf(bb, w2v, V0);
        }
        spU[q * DD + j] = U; spV[q * DD + j] = V; spV0[q * DD + j] = V0;
        __syncthreads();
        if (tid < DD) {
            sU[tid]  = spU[tid]  + spU[DD + tid]  + spU[2 * DD + tid]  + spU[3 * DD + tid];
            sV[tid]  = spV[tid]  + spV[DD + tid]  + spV[2 * DD + tid]  + spV[3 * DD + tid];
            sV0[tid] = spV0[tid] + spV0[DD + tid] + spV0[2 * DD + tid] + spV0[3 * DD + tid];
        }
        __syncthreads();
        if (tid < 16) {
            const int l = tid;
            const int j0 = 4 * l;
            __half2 U01 = __floats2half2_rn(sU[j0],     sU[j0 + 1]);
            __half2 U23 = __floats2half2_rn(sU[j0 + 2], sU[j0 + 3]);
            __half2 VP01 = __floats2half2_rn(sV[j0]     + sV0[j0]     + 2.0f * sb2v[j0],
                                             sV[j0 + 1] + sV0[j0 + 1] + 2.0f * sb2v[j0 + 1]);
            __half2 VP23 = __floats2half2_rn(sV[j0 + 2] + sV0[j0 + 2] + 2.0f * sb2v[j0 + 2],
                                             sV[j0 + 3] + sV0[j0 + 3] + 2.0f * sb2v[j0 + 3]);
            __half2 VS01 = __floats2half2_rn(sV[j0]     - sV0[j0],
                                             sV[j0 + 1] - sV0[j0 + 1]);
            __half2 VS23 = __floats2half2_rn(sV[j0 + 2] - sV0[j0 + 2],
                                             sV[j0 + 3] - sV0[j0 + 3]);
            g_TP4[m * 16 + l] = make_uint4(*(const uint32_t*)&U01, *(const uint32_t*)&U23,
                                           *(const uint32_t*)&VP01, *(const uint32_t*)&VP23);
            g_TS4[m * 16 + l] = make_uint4(*(const uint32_t*)&U01, *(const uint32_t*)&U23,
                                           *(const uint32_t*)&VS01, *(const uint32_t*)&VS23);
        }
        __threadfence();
        __syncthreads();
        if (tid == 0) atomicAdd(&g_done_cnt, 1);
    } else if (blk < NINT + 5) {
        // --- weight table chunk ---
        float* swt = sf; float* sbt = sf + TDIM; float* sws = sf + 2 * TDIM;
        if (tid < TDIM) {
            swt[tid] = w_time[tid];
            sbt[tid] = b_time[tid];
            sws[tid] = w_ts[tid];
        }
        __syncthreads();
        int g = (blk - NINT) * 256 + tid;
        if (g <= NT) {
            float t = (float)g * (2.0f / (float)NT);
            float acc = b_ts[0];
            #pragma unroll 4
            for (int k = 0; k < TDIM; ++k)
                acc = fmaf(__cosf(fmaf(t, swt[k], sbt[k])), sws[k], acc);
            g_W[g] = 1.0f / (1.0f + __expf(-acc));
        }
        __threadfence();
        __syncthreads();
        if (tid == 0) atomicAdd(&g_done_cnt, 1);
    } else if (blk < NSETUP) {
        // --- m-table chunk: 1024 entries, 4 per thread (x < 256 => <= 0x5C00) ---
        float* sTin = sf; float* sTs = sf + 64;
        build_sorted_thresholds(w1, b1, sTin, sTs, tid);
        const int base = (blk - (NINT + 5)) * 1024 + tid * 4;
        uint32_t packed = 0;
        #pragma unroll
        for (int e = 0; e < 4; ++e) {
            const unsigned short us = (unsigned short)(base + e);
            const float v = __half2float(__ushort_as_half(us));
            int m = 0;
            #pragma unroll
            for (int s = 32; s >= 1; s >>= 1)
                if (sTs[m + s - 1] < v) m += s;
            if (m < NTHR && sTs[m] < v) ++m;
            if (m > NTHR) m = NTHR;
            packed |= ((uint32_t)m & 255u) << (8 * e);
        }
        ((uint32_t*)g_M)[base >> 2] = packed;
        __threadfence();
        __syncthreads();
        if (tid == 0) atomicAdd(&g_done_cnt, 1);
    }
    __syncthreads();   // setup scratch dead; safe to overlay hash

    // ===================== Phase A: hash histogram (table-independent) ======
    const int b = blk;
    const int i = tid;

    #pragma unroll
    for (int t = 0; t < 2; ++t)
        ((int4*)sHash)[i + t * LL] = make_int4(0, 0, 0, 0);

    const int sid = src_ids[b * LL + i];
    const int did = dst_ids[b * LL + i];
    __syncthreads();

    int* keys = sHash;
    int* cnts = sHash + 1024;
    const int slot_s = hash_insert(keys, cnts, 0,   sid);  // sid in src table
    const int slot_d = hash_insert(keys, cnts, 512, did);  // did in dst table
    __syncthreads();

    // own-table counts: direct slot reads (no probe); cross-table: probe walks
    const int css = (slot_s >= 0) ? cnts[slot_s] : 0;
    const int cdd = (slot_d >= 0) ? cnts[slot_d] : 0;
    const int csd = hash_lookup(keys, cnts, 512, sid);
    const int cds = hash_lookup(keys, cnts, 0,   did);

    const float nt  = node_times[b];
    const float ts_ = nt - src_times[b * LL + i];
    const float td_ = nt - dst_times[b * LL + i];

    // ===================== single spin-gate: all setup pieces ===============
    if (i == 0) {
        while (atomicAdd(&g_done_cnt, 0) < NSETUP) __nanosleep(64);
    }
    __syncthreads();
    __threadfence();

    // ===================== weights, x, m ====================================
    const float ws = weight_lookup(ts_);
    const float wd = weight_lookup(td_);

    __half2 hxs = __floats2half2_rn((float)css * ws, (float)csd * ws);
    __half2 hxd = __floats2half2_rn((float)cds * wd, (float)cdd * wd);
    const uint32_t pk0 = *(const uint32_t*)&hxs;
    const uint32_t pk1 = *(const uint32_t*)&hxd;

    const uint32_t m_ss = __ldg(&g_M[pk0 & 0xFFFFu]);
    const uint32_t m_sd = __ldg(&g_M[pk0 >> 16]);
    const uint32_t m_ds = __ldg(&g_M[pk1 & 0xFFFFu]);
    const uint32_t m_dd = __ldg(&g_M[pk1 >> 16]);
    const uint32_t pkm = m_ss | (m_sd << 8) | (m_ds << 16) | (m_dd << 24);

    // ===================== Phase B: per-warp epilogue =======================
    const int wid  = i >> 5;
    const int lane = i & 31;
    const int lsub = lane & 15;
    const int hsel = lane >> 4;

    const uint4* __restrict__ TP = g_TP4;
    const uint4* __restrict__ TS = g_TS4;
    const size_t dst_off = (size_t)BB * LL * DD;
    const size_t brow = (size_t)b * LL;

    #pragma unroll 2
    for (int p0 = 0; p0 < 16; ++p0) {
        const int src = (p0 << 1) + hsel;
        const uint32_t qx = __shfl_sync(0xFFFFFFFFu, pk0, src);
        const uint32_t qy = __shfl_sync(0xFFFFFFFFu, pk1, src);
        const uint32_t mm = __shfl_sync(0xFFFFFFFFu, pkm, src);

        const uint32_t mss = mm & 255u;
        const uint32_t msd = (mm >> 8) & 255u;
        const uint32_t mds = (mm >> 16) & 255u;
        const uint32_t mdd = mm >> 24;

        const uint4 Ap = __ldg(&TP[mss * 16 + lsub]);
        const uint4 Dp = __ldg(&TP[mdd * 16 + lsub]);
        const uint4 Bs = ldg128_pred0(&TS[msd * 16 + lsub], qx & 0xFFFF0000u);
        const uint4 Cs = ldg128_pred0(&TS[mds * 16 + lsub], qy & 0x0000FFFFu);

        const __half2 hs = h2(qx);
        const __half2 hd = h2(qy);
        const __half2 xss2 = __low2half2(hs),  xsd2 = __high2half2(hs);
        const __half2 xds2 = __low2half2(hd),  xdd2 = __high2half2(hd);

        const __half2 rs01 = __hadd2(__hfma2(xss2, h2(Ap.x), h2(Ap.z)),
                                     __hfma2(xsd2, h2(Bs.x), h2(Bs.z)));
        const __half2 rs23 = __hadd2(__hfma2(xss2, h2(Ap.y), h2(Ap.w)),
                                     __hfma2(xsd2, h2(Bs.y), h2(Bs.w)));
        const __half2 rd01 = __hadd2(__hfma2(xdd2, h2(Dp.x), h2(Dp.z)),
                                     __hfma2(xds2, h2(Cs.x), h2(Cs.z)));
        const __half2 rd23 = __hadd2(__hfma2(xdd2, h2(Dp.y), h2(Dp.w)),
                                     __hfma2(xds2, h2(Cs.y), h2(Cs.w)));

        const float2 s0 = __half22float2(rs01);
        const float2 s1 = __half22float2(rs23);
        const float2 d0 = __half22float2(rd01);
        const float2 d1 = __half22float2(rd23);

        const int p = (wid << 5) + (p0 << 1) + hsel;
        const size_t rowbase = (brow + p) * DD + 4 * lsub;
        *(float4*)(out + rowbase)           = make_float4(s0.x, s0.y, s1.x, s1.y);
        *(float4*)(out + dst_off + rowbase) = make_float4(d0.x, d0.y, d1.x, d1.y);
    }

    // ===================== epilogue: reset counters for next replay =========
    __syncthreads();
    if (tid == 0) {
        int done = atomicAdd(&g_fin_cnt, 1);
        if (done == BB - 1) {
            g_done_cnt = 0;
            g_fin_cnt  = 0;
            __threadfence();
        }
    }
}

// ---------------------------------------------------------------------------
// Inputs: 0 src_ids, 1 dst_ids, 2 src_times, 3 dst_times, 4 node_times,
// 5 num_nodes (unused), 6 w_time, 7 b_time, 8 w_ts, 9 b_ts, 10 w1, 11 b1,
// 12 w2, 13 b2.  Output: [src_feats (B,L,D); dst_feats (B,L,D)].
// ---------------------------------------------------------------------------
extern "C" void kernel_launch(void* const* d_in, const int* in_sizes, int n_in,
                              void* d_out, int out_size) {
    const int*   src_ids    = (const int*)  d_in[0];
    const int*   dst_ids    = (const int*)  d_in[1];
    const float* src_times  = (const float*)d_in[2];
    const float* dst_times  = (const float*)d_in[3];
    const float* node_times = (const float*)d_in[4];
    const float* w_time     = (const float*)d_in[6];
    const float* b_time     = (const float*)d_in[7];
    const float* w_ts       = (const float*)d_in[8];
    const float* b_ts       = (const float*)d_in[9];
    const float* w1         = (const float*)d_in[10];
    const float* b1         = (const float*)d_in[11];
    const float* w2         = (const float*)d_in[12];
    const float* b2         = (const float*)d_in[13];
    float*       out        = (float*)d_out;

    tni_fused_kernel<<<BB, LL>>>(src_ids, dst_ids, src_times, dst_times,
                                 node_times, w_time, b_time, w_ts, b_ts,
                                 w1, b1, w2, b2, out);
}

// round 17
// speedup vs baseline: 1.3272x; 1.0083x over previous
#include <cuda_runtime.h>
#include <cuda_fp16.h>
#include <math_constants.h>
#include <cstdint>

#define BB 1024
#define LL 256
#define DD 64
#define TDIM 100
#define NTHR 64
#define NINT 65
#define NT 1024          // weight-table intervals (table has NT+1 entries)
#define MBLK 24          // m-table builder blocks (24 x 1024 = 24576 entries)
#define MENT (MBLK * 1024)   // covers half patterns up to 384.0 (x < 256.0 always)
#define NSETUP (NINT + 5 + MBLK)   // 94 setup blocks

// Scratch in __device__ globals (no allocations allowed).
// Row m = 16 uint4 per plane, each {U01,U23,V01,V23} (half2 words):
//   P: V'_m = V_m + V0 + 2*b2   (always-loaded operand)
//   S: V'_m = V_m - V0          (predicated; row contribution exactly 0 when x==0)
__device__ __align__(16) uint4 g_TP4[NINT * 16];
__device__ __align__(16) uint4 g_TS4[NINT * 16];
__device__ float g_W[NT + 1];                  // weight(t) table, t in [0,2]
__device__ __align__(16) uint8_t g_M[MENT];    // m(half_bits(x)) interval table
__device__ int g_done_cnt;                     // setup pieces done (reset per launch)
__device__ int g_fin_cnt;                      // blocks finished (reset per launch)

// ---------------------------------------------------------------------------
// Helpers (split-table hash: two 512-slot tables — low concurrent-insert
// density; the merged R12 table caused CAS-retry storms)
// ---------------------------------------------------------------------------
__device__ __forceinline__ unsigned hash_id(int id) {
    return ((unsigned)id * 2654435761u) >> 23;  // 9 bits -> [0,512)
}

// Insert id into table at base; returns ABSOLUTE slot index (or -1 for id==0).
__device__ __forceinline__ int hash_insert(int* keys, int* cnts, int base, int id) {
    if (id == 0) return -1;
    unsigned slot = hash_id(id) & 511u;
    while (true) {
        int prev = atomicCAS(&keys[base + slot], 0, id);
        if (prev == 0 || prev == id) {
            atomicAdd(&cnts[base + slot], 1);
            return base + (int)slot;
        }
        slot = (slot + 1) & 511u;
    }
}

__device__ __forceinline__ int hash_lookup(const int* keys, const int* cnts,
                                           int base, int id) {
    if (id == 0) return 0;
    unsigned slot = hash_id(id) & 511u;
    while (true) {
        int k = keys[base + slot];
        if (k == id) return cnts[base + slot];
        if (k == 0) return 0;
        slot = (slot + 1) & 511u;
    }
}

__device__ __forceinline__ float weight_lookup(float t) {
    float u = t * ((float)NT * 0.5f);
    u = fminf(fmaxf(u, 0.0f), (float)NT - 0.001f);
    int i0 = (int)u;
    float f = u - (float)i0;
    float a  = __ldg(&g_W[i0]);
    float bb = __ldg(&g_W[i0 + 1]);
    return fmaf(f, bb - a, a);
}

// Predicated global v4 load, zero fallback. cond!=0 => load; else {0,0,0,0}.
__device__ __forceinline__ uint4 ldg128_pred0(const uint4* addr, uint32_t cond) {
    uint4 r = make_uint4(0u, 0u, 0u, 0u);
    asm volatile(
        "{\n\t"
        ".reg .pred p;\n\t"
        "setp.ne.u32 p, %4, 0;\n\t"
        "@p ld.global.nc.v4.u32 {%0, %1, %2, %3}, [%5];\n\t"
        "}"
        : "+r"(r.x), "+r"(r.y), "+r"(r.z), "+r"(r.w)
        : "r"(cond), "l"(addr));
    return r;
}

// Streaming (write-through, no L2 allocate) 128-bit store: output is written
// once and never re-read — keep it from evicting the hot lookup tables in L2.
__device__ __forceinline__ void stg128_stream(float* addr, float4 v) {
    asm volatile("st.global.wt.v4.f32 [%0], {%1, %2, %3, %4};"
                 :: "l"(addr), "f"(v.x), "f"(v.y), "f"(v.z), "f"(v.w)
                 : "memory");
}

__device__ __forceinline__ __half2 h2(uint32_t u) { return *(const __half2*)&u; }

// Compute sorted relu thresholds into sTs (ascending, INF padded). Block-wide.
__device__ __forceinline__ void build_sorted_thresholds(
    const float* __restrict__ w1, const float* __restrict__ b1,
    float* sTin, float* sTs, int tid) {
    if (tid < NTHR) {
        float w = w1[tid], b = b1[tid];
        bool crossing = (w > 0.0f && b < 0.0f) || (w < 0.0f && b > 0.0f);
        sTin[tid] = crossing ? (-b / w) : CUDART_INF_F;
    }
    __syncthreads();
    if (tid < NTHR) {
        float t = sTin[tid];
        int rank = 0;
        #pragma unroll
        for (int j = 0; j < NTHR; ++j) {
            float tj = sTin[j];
            rank += (tj < t) || (tj == t && j < tid);
        }
        sTs[rank] = t;
    }
    __syncthreads();
}

// ---------------------------------------------------------------------------
// Single fused kernel. Block b handles batch row b.
// Blocks 0..NSETUP-1 additionally build one setup piece first, then publish
// via g_done_cnt. All blocks: hash phase (table-independent, overlaps setup),
// ONE spin-gate, then weight/m lookups + Phase B epilogue.
// Last finishing block resets the counters for the next graph replay.
// ---------------------------------------------------------------------------
__global__ __launch_bounds__(LL, 8) void tni_fused_kernel(
    const int*   __restrict__ src_ids,
    const int*   __restrict__ dst_ids,
    const float* __restrict__ src_times,
    const float* __restrict__ dst_times,
    const float* __restrict__ node_times,
    const float* __restrict__ w_time,
    const float* __restrict__ b_time,
    const float* __restrict__ w_ts,
    const float* __restrict__ b_ts,
    const float* __restrict__ w1,
    const float* __restrict__ b1,
    const float* __restrict__ w2,
    const float* __restrict__ b2,
    float*       __restrict__ out)
{
    __shared__ __align__(16) int sHash[2048];   // setup scratch, then keys|counts

    const int blk = blockIdx.x;
    const int tid = threadIdx.x;
    float* sf = (float*)sHash;                  // setup scratch overlay (<= 1280 floats)

    // ===================== setup pieces (blocks 0..NSETUP-1) ================
    if (blk < NINT) {
        // --- UV row m = blk ---
        float* sw1  = sf;        float* sb1 = sf + 64;
        float* sTin = sf + 128;  float* sTs = sf + 192;
        float* sb2v = sf + 256;
        float* spU  = sf + 320;  float* spV = sf + 576;  float* spV0 = sf + 832;
        float* sU   = sf + 1088; float* sV  = sf + 1152; float* sV0  = sf + 1216;

        if (tid < NTHR) { sw1[tid] = w1[tid]; sb1[tid] = b1[tid]; }
        if (tid < DD)   sb2v[tid] = b2[tid];
        __syncthreads();
        build_sorted_thresholds(w1, b1, sTin, sTs, tid);

        const int m = blk;
        float lo = (m == 0)        ? 0.0f         : sTs[m - 1];
        float hi = (m == NINT - 1) ? CUDART_INF_F : sTs[m];
        float mid;
        if (!isfinite(lo))      mid = 1.0f;
        else if (!isfinite(hi)) mid = lo * 2.0f + 1.0f;
        else                    mid = 0.5f * (lo + hi);

        const int j = tid & 63;
        const int q = tid >> 6;
        float U = 0.0f, V = 0.0f, V0 = 0.0f;
        #pragma unroll 4
        for (int k2 = q * 16; k2 < q * 16 + 16; ++k2) {
            float w = sw1[k2], bb = sb1[k2];
            float w2v = w2[k2 * DD + j];
            if (fmaf(mid, w, bb) > 0.0f) {
                U = fmaf(w, w2v, U);
                V = fmaf(bb, w2v, V);
            }
            if (bb > 0.0f) V0 = fmaf(bb, w2v, V0);
        }
        spU[q * DD + j] = U; spV[q * DD + j] = V; spV0[q * DD + j] = V0;
        __syncthreads();
        if (tid < DD) {
            sU[tid]  = spU[tid]  + spU[DD + tid]  + spU[2 * DD + tid]  + spU[3 * DD + tid];
            sV[tid]  = spV[tid]  + spV[DD + tid]  + spV[2 * DD + tid]  + spV[3 * DD + tid];
            sV0[tid] = spV0[tid] + spV0[DD + tid] + spV0[2 * DD + tid] + spV0[3 * DD + tid];
        }
        __syncthreads();
        if (tid < 16) {
            const int l = tid;
            const int j0 = 4 * l;
            __half2 U01 = __floats2half2_rn(sU[j0],     sU[j0 + 1]);
            __half2 U23 = __floats2half2_rn(sU[j0 + 2], sU[j0 + 3]);
            __half2 VP01 = __floats2half2_rn(sV[j0]     + sV0[j0]     + 2.0f * sb2v[j0],
                                             sV[j0 + 1] + sV0[j0 + 1] + 2.0f * sb2v[j0 + 1]);
            __half2 VP23 = __floats2half2_rn(sV[j0 + 2] + sV0[j0 + 2] + 2.0f * sb2v[j0 + 2],
                                             sV[j0 + 3] + sV0[j0 + 3] + 2.0f * sb2v[j0 + 3]);
            __half2 VS01 = __floats2half2_rn(sV[j0]     - sV0[j0],
                                             sV[j0 + 1] - sV0[j0 + 1]);
            __half2 VS23 = __floats2half2_rn(sV[j0 + 2] - sV0[j0 + 2],
                                             sV[j0 + 3] - sV0[j0 + 3]);
            g_TP4[m * 16 + l] = make_uint4(*(const uint32_t*)&U01, *(const uint32_t*)&U23,
                                           *(const uint32_t*)&VP01, *(const uint32_t*)&VP23);
            g_TS4[m * 16 + l] = make_uint4(*(const uint32_t*)&U01, *(const uint32_t*)&U23,
                                           *(const uint32_t*)&VS01, *(const uint32_t*)&VS23);
        }
        __threadfence();
        __syncthreads();
        if (tid == 0) atomicAdd(&g_done_cnt, 1);
    } else if (blk < NINT + 5) {
        // --- weight table chunk ---
        float* swt = sf; float* sbt = sf + TDIM; float* sws = sf + 2 * TDIM;
        if (tid < TDIM) {
            swt[tid] = w_time[tid];
            sbt[tid] = b_time[tid];
            sws[tid] = w_ts[tid];
        }
        __syncthreads();
        int g = (blk - NINT) * 256 + tid;
        if (g <= NT) {
            float t = (float)g * (2.0f / (float)NT);
            float acc = b_ts[0];
            #pragma unroll 4
            for (int k = 0; k < TDIM; ++k)
                acc = fmaf(__cosf(fmaf(t, swt[k], sbt[k])), sws[k], acc);
            g_W[g] = 1.0f / (1.0f + __expf(-acc));
        }
        __threadfence();
        __syncthreads();
        if (tid == 0) atomicAdd(&g_done_cnt, 1);
    } else if (blk < NSETUP) {
        // --- m-table chunk: 1024 entries, 4 per thread (x < 256 => <= 0x5C00) ---
        float* sTin = sf; float* sTs = sf + 64;
        build_sorted_thresholds(w1, b1, sTin, sTs, tid);
        const int base = (blk - (NINT + 5)) * 1024 + tid * 4;
        uint32_t packed = 0;
        #pragma unroll
        for (int e = 0; e < 4; ++e) {
            const unsigned short us = (unsigned short)(base + e);
            const float v = __half2float(__ushort_as_half(us));
            int m = 0;
            #pragma unroll
            for (int s = 32; s >= 1; s >>= 1)
                if (sTs[m + s - 1] < v) m += s;
            if (m < NTHR && sTs[m] < v) ++m;
            if (m > NTHR) m = NTHR;
            packed |= ((uint32_t)m & 255u) << (8 * e);
        }
        ((uint32_t*)g_M)[base >> 2] = packed;
        __threadfence();
        __syncthreads();
        if (tid == 0) atomicAdd(&g_done_cnt, 1);
    }
    __syncthreads();   // setup scratch dead; safe to overlay hash

    // ===================== Phase A: hash histogram (table-independent) ======
    const int b = blk;
    const int i = tid;

    #pragma unroll
    for (int t = 0; t < 2; ++t)
        ((int4*)sHash)[i + t * LL] = make_int4(0, 0, 0, 0);

    const int sid = src_ids[b * LL + i];
    const int did = dst_ids[b * LL + i];
    __syncthreads();

    int* keys = sHash;
    int* cnts = sHash + 1024;
    const int slot_s = hash_insert(keys, cnts, 0,   sid);  // sid in src table
    const int slot_d = hash_insert(keys, cnts, 512, did);  // did in dst table
    __syncthreads();

    // own-table counts: direct slot reads (no probe); cross-table: probe walks
    const int css = (slot_s >= 0) ? cnts[slot_s] : 0;
    const int cdd = (slot_d >= 0) ? cnts[slot_d] : 0;
    const int csd = hash_lookup(keys, cnts, 512, sid);
    const int cds = hash_lookup(keys, cnts, 0,   did);

    const float nt  = node_times[b];
    const float ts_ = nt - src_times[b * LL + i];
    const float td_ = nt - dst_times[b * LL + i];

    // ===================== single spin-gate: all setup pieces ===============
    if (i == 0) {
        while (atomicAdd(&g_done_cnt, 0) < NSETUP) __nanosleep(64);
    }
    __syncthreads();
    __threadfence();

    // ===================== weights, x, m ====================================
    const float ws = weight_lookup(ts_);
    const float wd = weight_lookup(td_);

    __half2 hxs = __floats2half2_rn((float)css * ws, (float)csd * ws);
    __half2 hxd = __floats2half2_rn((float)cds * wd, (float)cdd * wd);
    const uint32_t pk0 = *(const uint32_t*)&hxs;
    const uint32_t pk1 = *(const uint32_t*)&hxd;

    const uint32_t m_ss = __ldg(&g_M[pk0 & 0xFFFFu]);
    const uint32_t m_sd = __ldg(&g_M[pk0 >> 16]);
    const uint32_t m_ds = __ldg(&g_M[pk1 & 0xFFFFu]);
    const uint32_t m_dd = __ldg(&g_M[pk1 >> 16]);
    const uint32_t pkm = m_ss | (m_sd << 8) | (m_ds << 16) | (m_dd << 24);

    // ===================== Phase B: per-warp epilogue =======================
    const int wid  = i >> 5;
    const int lane = i & 31;
    const int lsub = lane & 15;
    const int hsel = lane >> 4;

    const uint4* __restrict__ TP = g_TP4;
    const uint4* __restrict__ TS = g_TS4;
    const size_t dst_off = (size_t)BB * LL * DD;
    const size_t brow = (size_t)b * LL;

    #pragma unroll 2
    for (int p0 = 0; p0 < 16; ++p0) {
        const int src = (p0 << 1) + hsel;
        const uint32_t qx = __shfl_sync(0xFFFFFFFFu, pk0, src);
        const uint32_t qy = __shfl_sync(0xFFFFFFFFu, pk1, src);
        const uint32_t mm = __shfl_sync(0xFFFFFFFFu, pkm, src);

        const uint32_t mss = mm & 255u;
        const uint32_t msd = (mm >> 8) & 255u;
        const uint32_t mds = (mm >> 16) & 255u;
        const uint32_t mdd = mm >> 24;

        const uint4 Ap = __ldg(&TP[mss * 16 + lsub]);
        const uint4 Dp = __ldg(&TP[mdd * 16 + lsub]);
        const uint4 Bs = ldg128_pred0(&TS[msd * 16 + lsub], qx & 0xFFFF0000u);
        const uint4 Cs = ldg128_pred0(&TS[mds * 16 + lsub], qy & 0x0000FFFFu);

        const __half2 hs = h2(qx);
        const __half2 hd = h2(qy);
        const __half2 xss2 = __low2half2(hs),  xsd2 = __high2half2(hs);
        const __half2 xds2 = __low2half2(hd),  xdd2 = __high2half2(hd);

        const __half2 rs01 = __hadd2(__hfma2(xss2, h2(Ap.x), h2(Ap.z)),
                                     __hfma2(xsd2, h2(Bs.x), h2(Bs.z)));
        const __half2 rs23 = __hadd2(__hfma2(xss2, h2(Ap.y), h2(Ap.w)),
                                     __hfma2(xsd2, h2(Bs.y), h2(Bs.w)));
        const __half2 rd01 = __hadd2(__hfma2(xdd2, h2(Dp.x), h2(Dp.z)),
                                     __hfma2(xds2, h2(Cs.x), h2(Cs.z)));
        const __half2 rd23 = __hadd2(__hfma2(xdd2, h2(Dp.y), h2(Dp.w)),
                                     __hfma2(xds2, h2(Cs.y), h2(Cs.w)));

        const float2 s0 = __half22float2(rs01);
        const float2 s1 = __half22float2(rs23);
        const float2 d0 = __half22float2(rd01);
        const float2 d1 = __half22float2(rd23);

        const int p = (wid << 5) + (p0 << 1) + hsel;
        const size_t rowbase = (brow + p) * DD + 4 * lsub;
        stg128_stream(out + rowbase,           make_float4(s0.x, s0.y, s1.x, s1.y));
        stg128_stream(out + dst_off + rowbase, make_float4(d0.x, d0.y, d1.x, d1.y));
    }

    // ===================== epilogue: reset counters for next replay =========
    __syncthreads();
    if (tid == 0) {
        int done = atomicAdd(&g_fin_cnt, 1);
        if (done == BB - 1) {
            g_done_cnt = 0;
            g_fin_cnt  = 0;
            __threadfence();
        }
    }
}

// ---------------------------------------------------------------------------
// Inputs: 0 src_ids, 1 dst_ids, 2 src_times, 3 dst_times, 4 node_times,
// 5 num_nodes (unused), 6 w_time, 7 b_time, 8 w_ts, 9 b_ts, 10 w1, 11 b1,
// 12 w2, 13 b2.  Output: [src_feats (B,L,D); dst_feats (B,L,D)].
// ---------------------------------------------------------------------------
extern "C" void kernel_launch(void* const* d_in, const int* in_sizes, int n_in,
                              void* d_out, int out_size) {
    const int*   src_ids    = (const int*)  d_in[0];
    const int*   dst_ids    = (const int*)  d_in[1];
    const float* src_times  = (const float*)d_in[2];
    const float* dst_times  = (const float*)d_in[3];
    const float* node_times = (const float*)d_in[4];
    const float* w_time     = (const float*)d_in[6];
    const float* b_time     = (const float*)d_in[7];
    const float* w_ts       = (const float*)d_in[8];
    const float* b_ts       = (const float*)d_in[9];
    const float* w1         = (const float*)d_in[10];
    const float* b1         = (const float*)d_in[11];
    const float* w2         = (const float*)d_in[12];
    const float* b2         = (const float*)d_in[13];
    float*       out        = (float*)d_out;

    tni_fused_kernel<<<BB, LL>>>(src_ids, dst_ids, src_times, dst_times,
                                 node_times, w_time, b_time, w_ts, b_ts,
                                 w1, b1, w2, b2, out);
}